// round 5
// baseline (speedup 1.0000x reference)
#include <cuda_runtime.h>
#include <cstdint>
#include <cstddef>

// Problem constants (fixed by the reference setup)
#define BB   2
#define MMT  64     // m (outer-mean dim)
#define NNT  256    // i / j
#define DDT  256    // d
#define HHT  256    // h
#define ROWS (BB*MMT*NNT)   // 32768 token rows (b,m,i)

// ---------------- scratch (device globals; no allocations allowed) ----------
__device__ float g_xn[ROWS * DDT];                       //  33.5 MB  layernormed x
__device__ float g_L [ROWS * HHT];                       //  33.5 MB  left  proj (masked)
__device__ float g_R [ROWS * HHT];                       //  33.5 MB  right proj (masked)
__device__ float g_outer[(size_t)BB * NNT * NNT * HHT];  // 134   MB  outer[b][i][j][h]
__device__ float g_maskf[ROWS];                          // float mask (b,m,i)
__device__ float g_cinv[BB * NNT * NNT];                 // 1/(64*(cnt+eps))
__device__ int   g_mask_mode;                            // 0=int32, 1=float32, 2=uint8

// ---------------- kernel 0a: detect mask dtype ------------------------------
// mask has 32768 elements. If serialized as uint8/bool the buffer is 32768 B;
// reading the first 8192 uint32 words (32768 B) is safe for every candidate
// dtype. int32 0/1 data -> every word in {0,1}. float32 0.0/1.0 data -> every
// word in {0, 0x3F800000}. uint8 0/1 data -> packed bytes, words like
// 0x00010001 appear, failing both tests.
__global__ void detect_mask_kernel(const unsigned int* p) {
    __shared__ int s_nonbin, s_nonfp;
    if (threadIdx.x == 0) { s_nonbin = 0; s_nonfp = 0; }
    __syncthreads();
    int nonbin = 0, nonfp = 0;
    for (int idx = threadIdx.x; idx < 8192; idx += 256) {
        unsigned int v = p[idx];
        if (v != 0u && v != 1u)           nonbin = 1;
        if (v != 0u && v != 0x3F800000u)  nonfp  = 1;
    }
    if (nonbin) atomicOr(&s_nonbin, 1);
    if (nonfp)  atomicOr(&s_nonfp, 1);
    __syncthreads();
    if (threadIdx.x == 0) {
        int mode;
        if      (!s_nonbin) mode = 0;   // int32 0/1
        else if (!s_nonfp)  mode = 1;   // float32 0.0/1.0
        else                mode = 2;   // uint8 / bool bytes
        g_mask_mode = mode;
    }
}

// ---------------- kernel 0b: expand mask to float ----------------------------
__global__ void expand_mask_kernel(const void* p) {
    int r = blockIdx.x * 256 + threadIdx.x;  // 0..32767
    int mode = g_mask_mode;
    float f;
    if (mode == 0)      f = (((const int*)p)[r]           != 0)    ? 1.0f : 0.0f;
    else if (mode == 1) f = (((const float*)p)[r]         != 0.0f) ? 1.0f : 0.0f;
    else                f = (((const unsigned char*)p)[r] != 0)    ? 1.0f : 0.0f;
    g_maskf[r] = f;
}

// ---------------- kernel 1: LayerNorm over d=256 (one block per row) --------
__global__ void __launch_bounds__(256) ln_kernel(const float* __restrict__ x,
                                                 const float* __restrict__ w,
                                                 const float* __restrict__ bvec) {
    __shared__ float red[256];
    __shared__ float s_mu, s_rstd;
    int row = blockIdx.x;
    int t = threadIdx.x;
    float v = x[(size_t)row * DDT + t];
    red[t] = v;
    __syncthreads();
    for (int s = 128; s > 0; s >>= 1) {
        if (t < s) red[t] += red[t + s];
        __syncthreads();
    }
    if (t == 0) s_mu = red[0] * (1.0f / DDT);
    __syncthreads();
    float mu = s_mu;
    float dv = v - mu;
    red[t] = dv * dv;
    __syncthreads();
    for (int s = 128; s > 0; s >>= 1) {
        if (t < s) red[t] += red[t + s];
        __syncthreads();
    }
    if (t == 0) s_rstd = rsqrtf(red[0] * (1.0f / DDT) + 1e-5f);
    __syncthreads();
    g_xn[(size_t)row * DDT + t] = dv * s_rstd * w[t] + bvec[t];
}

// ---------------- kernel 2: projections (SGEMM 32768x256 @ 256x256, x2) -----
// C tile 128x128, BK=16, 256 threads, 8x8 microtile.
// blockIdx.z = 0 -> (Wl, bl, g_L); 1 -> (Wr, br, g_R).
// Epilogue: (acc + bias[h]) * maskf[row]
__global__ void __launch_bounds__(256) proj_kernel(const float* __restrict__ Wl,
                                                   const float* __restrict__ bl,
                                                   const float* __restrict__ Wr,
                                                   const float* __restrict__ br) {
    __shared__ __align__(16) float As[16][132];   // [k][row], padded
    __shared__ __align__(16) float Bs[16][128];   // [k][n]

    const float* W    = blockIdx.z ? Wr : Wl;
    const float* bias = blockIdx.z ? br : bl;
    float*       Out  = blockIdx.z ? g_R : g_L;

    int tid = threadIdx.x;
    int tx = tid & 15, ty = tid >> 4;
    int r0 = blockIdx.y * 128;   // row tile
    int n0 = blockIdx.x * 128;   // h tile

    float acc[8][8];
#pragma unroll
    for (int i = 0; i < 8; i++)
#pragma unroll
        for (int j = 0; j < 8; j++) acc[i][j] = 0.0f;

    for (int kb = 0; kb < DDT; kb += 16) {
        // A tile: 128 rows x 16 k, transposed into As[k][row]
#pragma unroll
        for (int it = 0; it < 2; it++) {
            int f = it * 256 + tid;
            int row = f >> 2, kv = f & 3;
            float4 v = *(const float4*)&g_xn[(size_t)(r0 + row) * DDT + kb + kv * 4];
            As[kv * 4 + 0][row] = v.x;
            As[kv * 4 + 1][row] = v.y;
            As[kv * 4 + 2][row] = v.z;
            As[kv * 4 + 3][row] = v.w;
        }
        // B tile: 16 k x 128 n
#pragma unroll
        for (int it = 0; it < 2; it++) {
            int f = it * 256 + tid;
            int k = f >> 5, nv = f & 31;
            *(float4*)&Bs[k][nv * 4] =
                *(const float4*)&W[(size_t)(kb + k) * HHT + n0 + nv * 4];
        }
        __syncthreads();
#pragma unroll
        for (int k = 0; k < 16; k++) {
            float4 a0 = *(const float4*)&As[k][ty * 8];
            float4 a1 = *(const float4*)&As[k][ty * 8 + 4];
            float4 b0 = *(const float4*)&Bs[k][tx * 8];
            float4 b1 = *(const float4*)&Bs[k][tx * 8 + 4];
            float av[8] = {a0.x, a0.y, a0.z, a0.w, a1.x, a1.y, a1.z, a1.w};
            float bv[8] = {b0.x, b0.y, b0.z, b0.w, b1.x, b1.y, b1.z, b1.w};
#pragma unroll
            for (int i = 0; i < 8; i++)
#pragma unroll
                for (int j = 0; j < 8; j++)
                    acc[i][j] = fmaf(av[i], bv[j], acc[i][j]);
        }
        __syncthreads();
    }

    float bb[8];
#pragma unroll
    for (int j = 0; j < 8; j++) bb[j] = bias[n0 + tx * 8 + j];

#pragma unroll
    for (int i = 0; i < 8; i++) {
        int row = r0 + ty * 8 + i;
        float mf = g_maskf[row];
#pragma unroll
        for (int jv = 0; jv < 2; jv++) {
            float4 v;
            v.x = (acc[i][jv * 4 + 0] + bb[jv * 4 + 0]) * mf;
            v.y = (acc[i][jv * 4 + 1] + bb[jv * 4 + 1]) * mf;
            v.z = (acc[i][jv * 4 + 2] + bb[jv * 4 + 2]) * mf;
            v.w = (acc[i][jv * 4 + 3] + bb[jv * 4 + 3]) * mf;
            *(float4*)&Out[(size_t)row * HHT + n0 + tx * 8 + jv * 4] = v;
        }
    }
}

// ---------------- kernel 3: pair-count inverse -------------------------------
// cinv[b][i][j] = 1 / (64 * (sum_m mf[b,m,i]*mf[b,m,j] + 1e-5))
__global__ void __launch_bounds__(256) cnt_kernel() {
    int b = blockIdx.x >> 8;
    int i = blockIdx.x & 255;
    int j = threadIdx.x;
    __shared__ float mi[MMT];
    if (j < MMT) mi[j] = g_maskf[(b * MMT + j) * NNT + i];
    __syncthreads();
    float s = 0.0f;
#pragma unroll 8
    for (int m = 0; m < MMT; m++)
        s = fmaf(mi[m], g_maskf[(b * MMT + m) * NNT + j], s);
    g_cinv[((size_t)b * NNT + i) * NNT + j] = 1.0f / ((float)MMT * (s + 1e-5f));
}

// ---------------- kernel 4: masked outer-mean contraction over m -------------
// outer[b][i][j][h] = cinv[b][i][j] * sum_m L[b,m,i,h] * R[b,m,j,h]
// Block tile: 64(i) x 32(j) x 8(h), K=m=64 in chunks of 8.
// Thread micro: 8(i) x 4(j) x 2(h) = 64 accumulators.
// tid mapping: jg = tid&7 (j fastest -> conflict-free R reads per phase),
//              hg = (tid>>3)&3, ig = tid>>5 (constant per warp -> L broadcast).
__global__ void __launch_bounds__(256) outer_kernel() {
    __shared__ __align__(16) float Ls[8][8][68];  // [m][h][i] (+4 pad)
    __shared__ __align__(16) float Rs[8][8][32];  // [m][h][j]

    int tid = threadIdx.x;
    int hb = blockIdx.x;             // 0..31  -> h0 = hb*8
    int jb = blockIdx.y;             // 0..7   -> j0 = jb*32
    int zb = blockIdx.z;             // 0..7   -> b = zb>>2, i0 = (zb&3)*64
    int b  = zb >> 2;
    int i0 = (zb & 3) * 64;
    int j0 = jb * 32;
    int h0 = hb * 8;

    int jg = tid & 7;
    int hg = (tid >> 3) & 3;
    int ig = tid >> 5;

    float acc[8][4][2];
#pragma unroll
    for (int ii = 0; ii < 8; ii++)
#pragma unroll
        for (int jj = 0; jj < 4; jj++) { acc[ii][jj][0] = 0.0f; acc[ii][jj][1] = 0.0f; }

    for (int mc = 0; mc < MMT; mc += 8) {
        // Ls: 8m x 64i x 8h  (transpose h<->i while staging)
#pragma unroll
        for (int it = 0; it < 4; it++) {
            int f = it * 256 + tid;          // 0..1023 float4s
            int hv = f & 1;
            int li = (f >> 1) & 63;
            int lm = f >> 7;
            float4 v = *(const float4*)
                &g_L[(((size_t)(b * MMT + mc + lm) * NNT + i0 + li) * HHT) + h0 + hv * 4];
            Ls[lm][hv * 4 + 0][li] = v.x;
            Ls[lm][hv * 4 + 1][li] = v.y;
            Ls[lm][hv * 4 + 2][li] = v.z;
            Ls[lm][hv * 4 + 3][li] = v.w;
        }
        // Rs: 8m x 32j x 8h
#pragma unroll
        for (int it = 0; it < 2; it++) {
            int f = it * 256 + tid;          // 0..511 float4s
            int hv = f & 1;
            int lj = (f >> 1) & 31;
            int lm = f >> 6;
            float4 v = *(const float4*)
                &g_R[(((size_t)(b * MMT + mc + lm) * NNT + j0 + lj) * HHT) + h0 + hv * 4];
            Rs[lm][hv * 4 + 0][lj] = v.x;
            Rs[lm][hv * 4 + 1][lj] = v.y;
            Rs[lm][hv * 4 + 2][lj] = v.z;
            Rs[lm][hv * 4 + 3][lj] = v.w;
        }
        __syncthreads();
#pragma unroll
        for (int lm = 0; lm < 8; lm++) {
            float4 l00 = *(const float4*)&Ls[lm][hg * 2 + 0][ig * 8];
            float4 l01 = *(const float4*)&Ls[lm][hg * 2 + 0][ig * 8 + 4];
            float4 l10 = *(const float4*)&Ls[lm][hg * 2 + 1][ig * 8];
            float4 l11 = *(const float4*)&Ls[lm][hg * 2 + 1][ig * 8 + 4];
            float4 r0v = *(const float4*)&Rs[lm][hg * 2 + 0][jg * 4];
            float4 r1v = *(const float4*)&Rs[lm][hg * 2 + 1][jg * 4];
            float lv0[8] = {l00.x, l00.y, l00.z, l00.w, l01.x, l01.y, l01.z, l01.w};
            float lv1[8] = {l10.x, l10.y, l10.z, l10.w, l11.x, l11.y, l11.z, l11.w};
            float rv0[4] = {r0v.x, r0v.y, r0v.z, r0v.w};
            float rv1[4] = {r1v.x, r1v.y, r1v.z, r1v.w};
#pragma unroll
            for (int ii = 0; ii < 8; ii++)
#pragma unroll
                for (int jj = 0; jj < 4; jj++) {
                    acc[ii][jj][0] = fmaf(lv0[ii], rv0[jj], acc[ii][jj][0]);
                    acc[ii][jj][1] = fmaf(lv1[ii], rv1[jj], acc[ii][jj][1]);
                }
        }
        __syncthreads();
    }

#pragma unroll
    for (int ii = 0; ii < 8; ii++) {
        int gi = i0 + ig * 8 + ii;
#pragma unroll
        for (int jj = 0; jj < 4; jj++) {
            int gj = j0 + jg * 4 + jj;
            float ci = g_cinv[((size_t)b * NNT + gi) * NNT + gj];
            size_t base = (((size_t)b * NNT + gi) * NNT + gj) * HHT + h0 + hg * 2;
            float2 v;
            v.x = acc[ii][jj][0] * ci;
            v.y = acc[ii][jj][1] * ci;
            *(float2*)&g_outer[base] = v;
        }
    }
}

// ---------------- kernel 5: final GEMM  (131072 x 256) @ (256 x 256) + bo ---
__global__ void __launch_bounds__(256) final_kernel(const float* __restrict__ Wo,
                                                    const float* __restrict__ bo,
                                                    float* __restrict__ out) {
    __shared__ __align__(16) float As[16][132];
    __shared__ __align__(16) float Bs[16][128];

    int tid = threadIdx.x;
    int tx = tid & 15, ty = tid >> 4;
    int r0 = blockIdx.y * 128;   // bij row tile (0..1023 tiles)
    int n0 = blockIdx.x * 128;   // d tile (0..1)

    float acc[8][8];
#pragma unroll
    for (int i = 0; i < 8; i++)
#pragma unroll
        for (int j = 0; j < 8; j++) acc[i][j] = 0.0f;

    for (int kb = 0; kb < HHT; kb += 16) {
#pragma unroll
        for (int it = 0; it < 2; it++) {
            int f = it * 256 + tid;
            int row = f >> 2, kv = f & 3;
            float4 v = *(const float4*)&g_outer[(size_t)(r0 + row) * HHT + kb + kv * 4];
            As[kv * 4 + 0][row] = v.x;
            As[kv * 4 + 1][row] = v.y;
            As[kv * 4 + 2][row] = v.z;
            As[kv * 4 + 3][row] = v.w;
        }
#pragma unroll
        for (int it = 0; it < 2; it++) {
            int f = it * 256 + tid;
            int k = f >> 5, nv = f & 31;
            *(float4*)&Bs[k][nv * 4] =
                *(const float4*)&Wo[(size_t)(kb + k) * DDT + n0 + nv * 4];
        }
        __syncthreads();
#pragma unroll
        for (int k = 0; k < 16; k++) {
            float4 a0 = *(const float4*)&As[k][ty * 8];
            float4 a1 = *(const float4*)&As[k][ty * 8 + 4];
            float4 b0 = *(const float4*)&Bs[k][tx * 8];
            float4 b1 = *(const float4*)&Bs[k][tx * 8 + 4];
            float av[8] = {a0.x, a0.y, a0.z, a0.w, a1.x, a1.y, a1.z, a1.w};
            float bv[8] = {b0.x, b0.y, b0.z, b0.w, b1.x, b1.y, b1.z, b1.w};
#pragma unroll
            for (int i = 0; i < 8; i++)
#pragma unroll
                for (int j = 0; j < 8; j++)
                    acc[i][j] = fmaf(av[i], bv[j], acc[i][j]);
        }
        __syncthreads();
    }

    float bb[8];
#pragma unroll
    for (int j = 0; j < 8; j++) bb[j] = bo[n0 + tx * 8 + j];

#pragma unroll
    for (int i = 0; i < 8; i++) {
        size_t row = (size_t)(r0 + ty * 8 + i);
#pragma unroll
        for (int jv = 0; jv < 2; jv++) {
            float4 v;
            v.x = acc[i][jv * 4 + 0] + bb[jv * 4 + 0];
            v.y = acc[i][jv * 4 + 1] + bb[jv * 4 + 1];
            v.z = acc[i][jv * 4 + 2] + bb[jv * 4 + 2];
            v.w = acc[i][jv * 4 + 3] + bb[jv * 4 + 3];
            *(float4*)&out[row * DDT + n0 + tx * 8 + jv * 4] = v;
        }
    }
}

// ---------------- launch ------------------------------------------------------
extern "C" void kernel_launch(void* const* d_in, const int* in_sizes, int n_in,
                              void* d_out, int out_size) {
    // metadata order: x, mask, ln_w, ln_b, Wl, bl, Wr, br, Wo, bo
    const float* x    = (const float*)d_in[0];
    const void*  mask = d_in[1];
    const float* ln_w = (const float*)d_in[2];
    const float* ln_b = (const float*)d_in[3];
    const float* Wl   = (const float*)d_in[4];
    const float* bl   = (const float*)d_in[5];
    const float* Wr   = (const float*)d_in[6];
    const float* br   = (const float*)d_in[7];
    const float* Wo   = (const float*)d_in[8];
    const float* bo   = (const float*)d_in[9];
    float* out = (float*)d_out;

    detect_mask_kernel<<<1, 256>>>((const unsigned int*)mask);
    expand_mask_kernel<<<ROWS / 256, 256>>>(mask);
    ln_kernel<<<ROWS, 256>>>(x, ln_w, ln_b);
    proj_kernel<<<dim3(HHT / 128, ROWS / 128, 2), 256>>>(Wl, bl, Wr, br);
    cnt_kernel<<<BB * NNT, 256>>>();
    outer_kernel<<<dim3(HHT / 8, NNT / 32, BB * (NNT / 64)), 256>>>();
    final_kernel<<<dim3(DDT / 128, (BB * NNT * NNT) / 128), 256>>>(Wo, bo, out);
}